// round 10
// baseline (speedup 1.0000x reference)
#include <cuda_runtime.h>
#include <cuda_bf16.h>
#include <math.h>
#include <float.h>
#include <stdint.h>

#define B_N 8192
#define D_N 384
#define H_N 256
#define C_N 6
#define KMAX 16
#define KE   1152          // extended K = 3 * 384
#define NPART 2            // column halves (2 sub-lists each -> 4 global lists)

// ---------------- scratch (static device globals; no runtime alloc) ----------
__device__ float         g_sq[B_N];
__device__ int           g_k[B_N];
__device__ float         g_h[(size_t)B_N * H_N];
__device__ float         g_topv[4 * (size_t)B_N * KMAX];
__device__ int           g_topi[4 * (size_t)B_N * KMAX];
__device__ int           g_idx[(size_t)B_N * KMAX];
__device__ __nv_bfloat16 g_a[(size_t)B_N * KE];   // [hi | hi | lo]
__device__ __nv_bfloat16 g_b[(size_t)B_N * KE];   // [hi | lo | hi]

#define SWZ(o) ((o) ^ (((o) >> 3) & 0x70))

__device__ __forceinline__ uint32_t smem_addr_u32(const void* p) {
    uint32_t a;
    asm("{ .reg .u64 t; cvta.to.shared.u64 t, %1; cvt.u32.u64 %0, t; }"
        : "=r"(a) : "l"(p));
    return a;
}
__device__ __forceinline__ void cp16(uint32_t dst, const void* src) {
    asm volatile("cp.async.cg.shared.global [%0], [%1], 16;" :: "r"(dst), "l"(src));
}
__device__ __forceinline__ void cp_commit() {
    asm volatile("cp.async.commit_group;" ::: "memory");
}
__device__ __forceinline__ void ldsm4(uint32_t& r0, uint32_t& r1, uint32_t& r2,
                                     uint32_t& r3, uint32_t addr) {
    asm volatile("ldmatrix.sync.aligned.m8n8.x4.shared.b16 {%0,%1,%2,%3}, [%4];"
                 : "=r"(r0), "=r"(r1), "=r"(r2), "=r"(r3) : "r"(addr));
}
__device__ __forceinline__ void mma16816(float* c, const uint32_t* a,
                                         uint32_t b0, uint32_t b1) {
    asm volatile("mma.sync.aligned.m16n8k16.row.col.f32.bf16.bf16.f32 "
                 "{%0,%1,%2,%3}, {%4,%5,%6,%7}, {%8,%9}, {%0,%1,%2,%3};"
                 : "+f"(c[0]), "+f"(c[1]), "+f"(c[2]), "+f"(c[3])
                 : "r"(a[0]), "r"(a[1]), "r"(a[2]), "r"(a[3]),
                   "r"(b0), "r"(b1));
}
__device__ __forceinline__ void ins16(float* rv, unsigned short* rx, float kv,
                                      int col, float& cm) {
    int slot = 0;
    #pragma unroll
    for (int s = 1; s < 16; s++)
        if (rv[s] < rv[slot] || (rv[s] == rv[slot] && rx[s] > rx[slot])) slot = s;
    rv[slot] = kv; rx[slot] = (unsigned short)col;
    float nm = rv[0];
    #pragma unroll
    for (int s = 1; s < 16; s++) nm = fminf(nm, rv[s]);
    cm = nm;
}

// ---------------- K0: split x -> extended bf16 operands ----------------------
__global__ void k_cvt(const float* __restrict__ x) {
    int row = blockIdx.x;
    int k   = threadIdx.x;                     // 384 threads
    float v = x[(size_t)row * D_N + k];
    __nv_bfloat16 hi = __float2bfloat16(v);
    __nv_bfloat16 lo = __float2bfloat16(v - __bfloat162float(hi));
    size_t base = (size_t)row * KE;
    g_a[base + k]       = hi;
    g_a[base + 384 + k] = hi;
    g_a[base + 768 + k] = lo;
    g_b[base + k]       = hi;
    g_b[base + 384 + k] = lo;
    g_b[base + 768 + k] = hi;
}

// ---------------- K1: sq[i] = ||x_i||^2 ; tau -> k ---------------------------
__global__ void k_sqtau(const float* __restrict__ x,
                        const float* __restrict__ Wtau,
                        const float* __restrict__ btau) {
    int row  = blockIdx.x * 8 + threadIdx.y;
    int lane = threadIdx.x;
    const float* xr = x + (size_t)row * D_N;
    float s = 0.f, t = 0.f;
    for (int i = lane; i < D_N; i += 32) {
        float v = xr[i];
        s = fmaf(v, v, s);
        t = fmaf(v, Wtau[i], t);
    }
    #pragma unroll
    for (int o = 16; o; o >>= 1) {
        s += __shfl_down_sync(0xffffffffu, s, o);
        t += __shfl_down_sync(0xffffffffu, t, o);
    }
    if (lane == 0) {
        g_sq[row] = s;
        float tau = 1.f / (1.f + expf(-(t + btau[0])));
        float kf  = rintf(16.f - 12.f * tau);
        kf = fminf(fmaxf(kf, 1.f), 16.f);
        g_k[row] = (int)kf;
    }
}

// ---------------- K2: h = relu(x @ W_proj + b_proj) --------------------------
__global__ __launch_bounds__(256) void k_proj(const float* __restrict__ x,
                                              const float* __restrict__ W,
                                              const float* __restrict__ bias) {
    __shared__ float As[16][68];
    __shared__ float Bs[16][68];
    int tid = threadIdx.x, tx = tid & 15, ty = tid >> 4;
    int mb = blockIdx.y * 64, nb = blockIdx.x * 64;
    float acc[4][4] = {};
    for (int kb = 0; kb < D_N; kb += 16) {
        {
            int r = tid >> 2, kq = (tid & 3) * 4;
            float4 va = *(const float4*)(x + (size_t)(mb + r) * D_N + kb + kq);
            As[kq + 0][r] = va.x; As[kq + 1][r] = va.y;
            As[kq + 2][r] = va.z; As[kq + 3][r] = va.w;
        }
        {
            int kr = tid >> 4, c = (tid & 15) * 4;
            float4 vb = *(const float4*)(W + (size_t)(kb + kr) * H_N + nb + c);
            *(float4*)&Bs[kr][c] = vb;
        }
        __syncthreads();
        #pragma unroll
        for (int k = 0; k < 16; k++) {
            float a[4], bv[4];
            #pragma unroll
            for (int i = 0; i < 4; i++) a[i] = As[k][ty * 4 + i];
            #pragma unroll
            for (int j = 0; j < 4; j++) bv[j] = Bs[k][tx * 4 + j];
            #pragma unroll
            for (int i = 0; i < 4; i++)
                #pragma unroll
                for (int j = 0; j < 4; j++)
                    acc[i][j] = fmaf(a[i], bv[j], acc[i][j]);
        }
        __syncthreads();
    }
    #pragma unroll
    for (int i = 0; i < 4; i++) {
        int row = mb + ty * 4 + i;
        #pragma unroll
        for (int j = 0; j < 4; j++) {
            int col = nb + tx * 4 + j;
            float v = acc[i][j] + bias[col];
            g_h[(size_t)row * H_N + col] = v > 0.f ? v : 0.f;
        }
    }
}

// ---------------- K3: HMMA x@x.T, 128x128 tile, 4x2 warps, frag dbuf ---------
// grid (64 row-tiles, 2 col-halves); 256 threads; 1 CTA/SM (no reg cap)
// SMEM per stage: A 16KB + B 16KB = 32KB; 3 stages; then lists
#define NN_STAGE    32768
#define NN_BOFF     16384
#define NN_TV_OFF   (3 * NN_STAGE)                   // 98304
#define NN_TI_OFF   (NN_TV_OFF + 256 * 16 * 4)       // 114688
#define NN_TMIN_OFF (NN_TI_OFF + 256 * 16 * 2)       // 122880
#define NN_SQC_OFF  (NN_TMIN_OFF + 256 * 4)          // 123904
#define NN_SMEM     (NN_SQC_OFF + 2 * 128 * 4)       // 124928
#define NN_TILES    (4096 / 128)     // 32 col tiles per half
#define NN_SLABS    18               // 1152 / 64

__device__ __forceinline__ void load_slab(uint32_t smem_u32, int stage,
                                          int mb, int cb, int t, int tid) {
    uint32_t sbase = smem_u32 + stage * NN_STAGE;
    #pragma unroll
    for (int i = 0; i < 4; i++) {
        int c = tid + i * 256;
        int row = c >> 3, j = c & 7;
        uint32_t dst = SWZ((uint32_t)(row * 128 + j * 16));
        cp16(sbase + dst, g_a + (size_t)(mb + row) * KE + t * 64 + j * 8);
        cp16(sbase + NN_BOFF + dst, g_b + (size_t)(cb + row) * KE + t * 64 + j * 8);
    }
    cp_commit();
}

__global__ __launch_bounds__(256, 1) void k_nn() {
    extern __shared__ __align__(1024) char smem[];
    uint32_t smem_u32 = smem_addr_u32(smem);
    float*          tv   = (float*)(smem + NN_TV_OFF);    // 256 lists x 16
    unsigned short* ti   = (unsigned short*)(smem + NN_TI_OFF);
    float*          tmin = (float*)(smem + NN_TMIN_OFF);  // 256
    float*          sqc  = (float*)(smem + NN_SQC_OFF);   // [2][128]

    int tid = threadIdx.x, lane = tid & 31, wid = tid >> 5;
    int mr = wid >> 1, nc = wid & 1;
    int mb = blockIdx.x * 128;
    int colbase = blockIdx.y * 4096;

    for (int i = tid; i < 256 * 16; i += 256) { tv[i] = -FLT_MAX; ti[i] = 0xFFFF; }
    tmin[tid] = -FLT_MAX;

    int lrow = lane & 15, lkoff = (lane >> 4) * 16;
    int q4 = lane & 3;
    int rb0 = mr * 32 + (lane >> 2);      // epilogue rows rb0, +8, +16, +24

    // prologue: stages 0,1 of tile 0 + sq
    load_slab(smem_u32, 0, mb, colbase, 0, tid);
    load_slab(smem_u32, 1, mb, colbase, 1, tid);
    if (tid < 128) sqc[tid] = g_sq[colbase + tid];

    #pragma unroll 1
    for (int ct = 0; ct < NN_TILES; ct++) {
        float acc[2][8][4];
        #pragma unroll
        for (int mi = 0; mi < 2; mi++)
            #pragma unroll
            for (int ni = 0; ni < 8; ni++)
                #pragma unroll
                for (int q = 0; q < 4; q++) acc[mi][ni][q] = 0.f;

        #pragma unroll 1
        for (int s = 0; s < NN_SLABS; s++) {
            if (s == NN_SLABS - 1)
                asm volatile("cp.async.wait_group 0;" ::: "memory");
            else
                asm volatile("cp.async.wait_group 1;" ::: "memory");
            __syncthreads();

            if (s + 2 < NN_SLABS)
                load_slab(smem_u32, (s + 2) % 3, mb, colbase + ct * 128, s + 2, tid);

            uint32_t sbase = smem_u32 + (s % 3) * NN_STAGE;
            uint32_t aBase = sbase;
            uint32_t bBase = sbase + NN_BOFF;

            // fragment double buffer: load kk+1 before kk's MMAs
            uint32_t af[2][2][4], bfr[2][4][4];
            {
                int arow = mr * 32 + lrow, brow = nc * 64 + lrow;
                #pragma unroll
                for (int mi = 0; mi < 2; mi++)
                    ldsm4(af[0][mi][0], af[0][mi][1], af[0][mi][2], af[0][mi][3],
                          aBase + SWZ((uint32_t)((arow + mi * 16) * 128 + lkoff)));
                #pragma unroll
                for (int ni = 0; ni < 4; ni++)
                    ldsm4(bfr[0][ni][0], bfr[0][ni][1], bfr[0][ni][2], bfr[0][ni][3],
                          bBase + SWZ((uint32_t)((brow + ni * 16) * 128 + lkoff)));
            }
            #pragma unroll
            for (int kk = 0; kk < 4; kk++) {
                int cur = kk & 1, nxt = cur ^ 1;
                if (kk < 3) {
                    int ko = (kk + 1) * 32 + lkoff;
                    int arow = mr * 32 + lrow, brow = nc * 64 + lrow;
                    #pragma unroll
                    for (int mi = 0; mi < 2; mi++)
                        ldsm4(af[nxt][mi][0], af[nxt][mi][1], af[nxt][mi][2], af[nxt][mi][3],
                              aBase + SWZ((uint32_t)((arow + mi * 16) * 128 + ko)));
                    #pragma unroll
                    for (int ni = 0; ni < 4; ni++)
                        ldsm4(bfr[nxt][ni][0], bfr[nxt][ni][1], bfr[nxt][ni][2], bfr[nxt][ni][3],
                              bBase + SWZ((uint32_t)((brow + ni * 16) * 128 + ko)));
                }
                #pragma unroll
                for (int mi = 0; mi < 2; mi++)
                    #pragma unroll
                    for (int ni = 0; ni < 4; ni++) {
                        mma16816(acc[mi][ni * 2 + 0], af[cur][mi],
                                 bfr[cur][ni][0], bfr[cur][ni][2]);
                        mma16816(acc[mi][ni * 2 + 1], af[cur][mi],
                                 bfr[cur][ni][1], bfr[cur][ni][3]);
                    }
            }
        }

        // prefetch next tile stages 0,1 + sq (overlaps epilogue)
        if (ct + 1 < NN_TILES) {
            int cbn = colbase + (ct + 1) * 128;
            load_slab(smem_u32, 0, mb, cbn, 0, tid);
            load_slab(smem_u32, 1, mb, cbn, 1, tid);
            if (tid < 128) sqc[((ct + 1) & 1) * 128 + tid] = g_sq[cbn + tid];
        }

        // ---- register epilogue: 4 rows/lane, per (row, nc) lists ----
        const float* sqp = sqc + (ct & 1) * 128;
        float m0 = tmin[(rb0)      * 2 + nc];
        float m1 = tmin[(rb0 + 8)  * 2 + nc];
        float m2 = tmin[(rb0 + 16) * 2 + nc];
        float m3 = tmin[(rb0 + 24) * 2 + nc];
        bool hit = false;
        #pragma unroll
        for (int mi = 0; mi < 2; mi++) {
            float ma = mi ? m2 : m0, mb2 = mi ? m3 : m1;
            #pragma unroll
            for (int ni = 0; ni < 8; ni++) {
                int c0 = nc * 64 + ni * 8 + 2 * q4;
                float s0 = sqp[c0], s1 = sqp[c0 + 1];
                float k0 = fmaf(2.f, acc[mi][ni][0], -s0);
                float k1 = fmaf(2.f, acc[mi][ni][1], -s1);
                float k2 = fmaf(2.f, acc[mi][ni][2], -s0);
                float k3 = fmaf(2.f, acc[mi][ni][3], -s1);
                hit |= (k0 > ma) | (k1 > ma) | (k2 > mb2) | (k3 > mb2);
            }
        }
        unsigned mask = __ballot_sync(0xffffffffu, hit);
        if (mask) {
            #pragma unroll 1
            for (int phase = 0; phase < 4; phase++) {
                if (q4 == phase && hit) {
                    #pragma unroll 1
                    for (int mi = 0; mi < 2; mi++) {
                        int ra = rb0 + mi * 16, rbq = ra + 8;
                        float cma = tmin[ra * 2 + nc], cmb = tmin[rbq * 2 + nc];
                        float* rva = tv + (ra * 2 + nc) * 16;
                        float* rvb = tv + (rbq * 2 + nc) * 16;
                        unsigned short* rxa = ti + (ra * 2 + nc) * 16;
                        unsigned short* rxb = ti + (rbq * 2 + nc) * 16;
                        #pragma unroll 1
                        for (int ni = 0; ni < 8; ni++) {
                            int cl = nc * 64 + ni * 8 + 2 * q4;
                            float s0 = sqp[cl], s1 = sqp[cl + 1];
                            float k0 = fmaf(2.f, acc[mi][ni][0], -s0);
                            float k1 = fmaf(2.f, acc[mi][ni][1], -s1);
                            float k2 = fmaf(2.f, acc[mi][ni][2], -s0);
                            float k3 = fmaf(2.f, acc[mi][ni][3], -s1);
                            int c0 = ct * 128 + cl;
                            if (k0 > cma) ins16(rva, rxa, k0, c0, cma);
                            if (k1 > cma) ins16(rva, rxa, k1, c0 + 1, cma);
                            if (k2 > cmb) ins16(rvb, rxb, k2, c0, cmb);
                            if (k3 > cmb) ins16(rvb, rxb, k3, c0 + 1, cmb);
                        }
                        tmin[ra * 2 + nc] = cma; tmin[rbq * 2 + nc] = cmb;
                    }
                }
                __syncwarp();
            }
        }
    }

    __syncthreads();

    // ---- sort each of the 256 lists by (v desc, idx asc) and write out ----
    {
        float* rv = tv + tid * 16;
        unsigned short* rx = ti + tid * 16;
        for (int a = 1; a < 16; a++) {
            float v = rv[a]; int id = rx[a]; int b2 = a - 1;
            while (b2 >= 0 && (rv[b2] < v || (rv[b2] == v && rx[b2] > id))) {
                rv[b2 + 1] = rv[b2]; rx[b2 + 1] = rx[b2]; b2--;
            }
            rv[b2 + 1] = v; rx[b2 + 1] = (unsigned short)id;
        }
        int row = mb + (tid >> 1);
        int l   = blockIdx.y * 2 + (tid & 1);
        size_t base = ((size_t)l * B_N + row) * KMAX;
        for (int s = 0; s < 16; s++) {
            g_topv[base + s] = rv[s];
            g_topi[base + s] = colbase + (int)rx[s];
        }
    }
}

// ---------------- K3b: 4-way merge of per-list top-16 -----------------------
__global__ void k_merge() {
    int row = blockIdx.x * 256 + threadIdx.x;
    if (row >= B_N) return;
    const float* V[4]; const int* I[4];
    int a[4];
    #pragma unroll
    for (int l = 0; l < 4; l++) {
        V[l] = g_topv + ((size_t)l * B_N + row) * KMAX;
        I[l] = g_topi + ((size_t)l * B_N + row) * KMAX;
        a[l] = 0;
    }
    int* out = g_idx + (size_t)row * KMAX;
    for (int s = 0; s < 16; s++) {
        int bl = -1; float bv = 0.f; int bi = 0;
        #pragma unroll
        for (int l = 0; l < 4; l++) {
            float v = V[l][a[l]]; int id = I[l][a[l]];
            if (bl < 0 || v > bv || (v == bv && id < bi)) { bl = l; bv = v; bi = id; }
        }
        out[s] = bi; a[bl]++;
    }
}

// ---------------- K4: gather-mean -> W_res -> relu -> +h -> LN -> fc ---------
__global__ __launch_bounds__(256) void k_tail(const float* __restrict__ Wres,
                                              const float* __restrict__ bres,
                                              const float* __restrict__ lng,
                                              const float* __restrict__ lnb,
                                              const float* __restrict__ Wfc,
                                              const float* __restrict__ bfc,
                                              float* __restrict__ out) {
    extern __shared__ float sm[];
    float* agg  = sm;
    float* hs   = agg + 16 * H_N;
    float* Ws   = hs + 16 * H_N;
    int*   idxs = (int*)(Ws + 32 * H_N);
    int*   ks   = idxs + 16 * 16;

    int tid = threadIdx.x;
    int rb = blockIdx.x * 16;
    {
        int r = tid >> 4, j = tid & 15;
        idxs[tid] = g_idx[(size_t)(rb + r) * KMAX + j];
    }
    if (tid < 16) ks[tid] = g_k[rb + tid];
    __syncthreads();

    int c = tid;
    for (int r = 0; r < 16; r++) {
        int kr = ks[r];
        float s = 0.f;
        for (int j = 0; j < kr; j++)
            s += g_h[(size_t)idxs[r * 16 + j] * H_N + c];
        agg[r * H_N + c] = s / (float)kr;
        hs[r * H_N + c]  = g_h[(size_t)(rb + r) * H_N + c];
    }
    __syncthreads();

    float acc[16];
    #pragma unroll
    for (int r = 0; r < 16; r++) acc[r] = 0.f;
    for (int kb = 0; kb < H_N; kb += 32) {
        __syncthreads();
        for (int kk = 0; kk < 32; kk++)
            Ws[kk * H_N + c] = Wres[(size_t)(kb + kk) * H_N + c];
        __syncthreads();
        for (int kk = 0; kk < 32; kk++) {
            float w = Ws[kk * H_N + c];
            #pragma unroll
            for (int r = 0; r < 16; r++)
                acc[r] = fmaf(agg[r * H_N + kb + kk], w, acc[r]);
        }
    }
    __syncthreads();

    float brc = bres[c];
    for (int r = 0; r < 16; r++) {
        float rv = acc[r] + brc;
        rv = rv > 0.f ? rv : 0.f;
        agg[r * H_N + c] = hs[r * H_N + c] + rv;
    }
    __syncthreads();

    int lane = tid & 31, wid = tid >> 5;
    for (int rr = 0; rr < 2; rr++) {
        int r = wid * 2 + rr;
        int row = rb + r;
        float* z = agg + r * H_N;
        float s = 0.f;
        #pragma unroll
        for (int t = 0; t < 8; t++) s += z[lane + 32 * t];
        #pragma unroll
        for (int o = 16; o; o >>= 1) s += __shfl_xor_sync(0xffffffffu, s, o);
        float mu = s * (1.f / 256.f);
        float vs = 0.f;
        #pragma unroll
        for (int t = 0; t < 8; t++) {
            float d = z[lane + 32 * t] - mu;
            vs = fmaf(d, d, vs);
        }
        #pragma unroll
        for (int o = 16; o; o >>= 1) vs += __shfl_xor_sync(0xffffffffu, vs, o);
        float rstd = rsqrtf(vs * (1.f / 256.f) + 1e-5f);

        float vals[8];
        #pragma unroll
        for (int t = 0; t < 8; t++) {
            int col = lane + 32 * t;
            float zn = (z[col] - mu) * rstd;
            vals[t] = zn * lng[col] + lnb[col];
        }
        #pragma unroll
        for (int cc = 0; cc < C_N; cc++) {
            float p = 0.f;
            #pragma unroll
            for (int t = 0; t < 8; t++) {
                int col = lane + 32 * t;
                p = fmaf(vals[t], Wfc[(size_t)col * C_N + cc], p);
            }
            #pragma unroll
            for (int o = 16; o; o >>= 1) p += __shfl_xor_sync(0xffffffffu, p, o);
            if (lane == 0) out[(size_t)row * C_N + cc] = p + bfc[cc];
        }
    }
}

// ---------------- launch ------------------------------------------------------
extern "C" void kernel_launch(void* const* d_in, const int* in_sizes, int n_in,
                              void* d_out, int out_size) {
    const float* x  = (const float*)d_in[0];
    const float* Wp = (const float*)d_in[1];
    const float* bp = (const float*)d_in[2];
    const float* Wt = (const float*)d_in[3];
    const float* bt = (const float*)d_in[4];
    const float* Wr = (const float*)d_in[5];
    const float* br = (const float*)d_in[6];
    const float* lg = (const float*)d_in[7];
    const float* lb = (const float*)d_in[8];
    const float* Wf = (const float*)d_in[9];
    const float* bf = (const float*)d_in[10];
    float* out = (float*)d_out;

    const int SMEM_TAIL = (16 * 256 * 2 + 32 * 256 + 16 * 16 + 16) * 4;
    cudaFuncSetAttribute(k_tail, cudaFuncAttributeMaxDynamicSharedMemorySize, SMEM_TAIL);
    cudaFuncSetAttribute(k_nn,   cudaFuncAttributeMaxDynamicSharedMemorySize, NN_SMEM);

    k_cvt<<<B_N, D_N>>>(x);
    k_sqtau<<<B_N / 8, dim3(32, 8)>>>(x, Wt, bt);
    k_proj<<<dim3(H_N / 64, B_N / 64), 256>>>(x, Wp, bp);
    k_nn<<<dim3(B_N / 128, NPART), 256, NN_SMEM>>>();
    k_merge<<<B_N / 256, 256>>>();
    k_tail<<<B_N / 16, 256, SMEM_TAIL>>>(Wr, br, lg, lb, Wf, bf, out);
}

// round 11
// speedup vs baseline: 1.6033x; 1.6033x over previous
#include <cuda_runtime.h>
#include <cuda_bf16.h>
#include <math.h>
#include <float.h>
#include <stdint.h>

#define B_N 8192
#define D_N 384
#define H_N 256
#define C_N 6
#define KMAX 16
#define KE   1152          // extended K = 3 * 384
#define NPART 4            // column quarters; x2 nc sub-lists -> 8 global lists

// ---------------- scratch (static device globals; no runtime alloc) ----------
__device__ float         g_sq[B_N];
__device__ int           g_k[B_N];
__device__ float         g_h[(size_t)B_N * H_N];
__device__ float         g_topv[8 * (size_t)B_N * KMAX];
__device__ int           g_topi[8 * (size_t)B_N * KMAX];
__device__ int           g_idx[(size_t)B_N * KMAX];
__device__ __nv_bfloat16 g_a[(size_t)B_N * KE];   // [hi | hi | lo]
__device__ __nv_bfloat16 g_b[(size_t)B_N * KE];   // [hi | lo | hi]

#define SWZ(o) ((o) ^ (((o) >> 3) & 0x70))

__device__ __forceinline__ uint32_t smem_addr_u32(const void* p) {
    uint32_t a;
    asm("{ .reg .u64 t; cvta.to.shared.u64 t, %1; cvt.u32.u64 %0, t; }"
        : "=r"(a) : "l"(p));
    return a;
}
__device__ __forceinline__ void cp16(uint32_t dst, const void* src) {
    asm volatile("cp.async.cg.shared.global [%0], [%1], 16;" :: "r"(dst), "l"(src));
}
__device__ __forceinline__ void cp_commit() {
    asm volatile("cp.async.commit_group;" ::: "memory");
}
__device__ __forceinline__ void ldsm4(uint32_t& r0, uint32_t& r1, uint32_t& r2,
                                     uint32_t& r3, uint32_t addr) {
    asm volatile("ldmatrix.sync.aligned.m8n8.x4.shared.b16 {%0,%1,%2,%3}, [%4];"
                 : "=r"(r0), "=r"(r1), "=r"(r2), "=r"(r3) : "r"(addr));
}
__device__ __forceinline__ void mma16816(float* c, const uint32_t* a,
                                         uint32_t b0, uint32_t b1) {
    asm volatile("mma.sync.aligned.m16n8k16.row.col.f32.bf16.bf16.f32 "
                 "{%0,%1,%2,%3}, {%4,%5,%6,%7}, {%8,%9}, {%0,%1,%2,%3};"
                 : "+f"(c[0]), "+f"(c[1]), "+f"(c[2]), "+f"(c[3])
                 : "r"(a[0]), "r"(a[1]), "r"(a[2]), "r"(a[3]),
                   "r"(b0), "r"(b1));
}
__device__ __forceinline__ void ins16(float* rv, unsigned short* rx, float kv,
                                      int col, float& cm) {
    int slot = 0;
    #pragma unroll
    for (int s = 1; s < 16; s++)
        if (rv[s] < rv[slot] || (rv[s] == rv[slot] && rx[s] > rx[slot])) slot = s;
    rv[slot] = kv; rx[slot] = (unsigned short)col;
    float nm = rv[0];
    #pragma unroll
    for (int s = 1; s < 16; s++) nm = fminf(nm, rv[s]);
    cm = nm;
}

// ---------------- K0: split x -> extended bf16 operands ----------------------
__global__ void k_cvt(const float* __restrict__ x) {
    int row = blockIdx.x;
    int k   = threadIdx.x;                     // 384 threads
    float v = x[(size_t)row * D_N + k];
    __nv_bfloat16 hi = __float2bfloat16(v);
    __nv_bfloat16 lo = __float2bfloat16(v - __bfloat162float(hi));
    size_t base = (size_t)row * KE;
    g_a[base + k]       = hi;
    g_a[base + 384 + k] = hi;
    g_a[base + 768 + k] = lo;
    g_b[base + k]       = hi;
    g_b[base + 384 + k] = lo;
    g_b[base + 768 + k] = hi;
}

// ---------------- K1: sq[i] = ||x_i||^2 ; tau -> k ---------------------------
__global__ void k_sqtau(const float* __restrict__ x,
                        const float* __restrict__ Wtau,
                        const float* __restrict__ btau) {
    int row  = blockIdx.x * 8 + threadIdx.y;
    int lane = threadIdx.x;
    const float* xr = x + (size_t)row * D_N;
    float s = 0.f, t = 0.f;
    for (int i = lane; i < D_N; i += 32) {
        float v = xr[i];
        s = fmaf(v, v, s);
        t = fmaf(v, Wtau[i], t);
    }
    #pragma unroll
    for (int o = 16; o; o >>= 1) {
        s += __shfl_down_sync(0xffffffffu, s, o);
        t += __shfl_down_sync(0xffffffffu, t, o);
    }
    if (lane == 0) {
        g_sq[row] = s;
        float tau = 1.f / (1.f + expf(-(t + btau[0])));
        float kf  = rintf(16.f - 12.f * tau);
        kf = fminf(fmaxf(kf, 1.f), 16.f);
        g_k[row] = (int)kf;
    }
}

// ---------------- K2: h = relu(x @ W_proj + b_proj) --------------------------
__global__ __launch_bounds__(256) void k_proj(const float* __restrict__ x,
                                              const float* __restrict__ W,
                                              const float* __restrict__ bias) {
    __shared__ float As[16][68];
    __shared__ float Bs[16][68];
    int tid = threadIdx.x, tx = tid & 15, ty = tid >> 4;
    int mb = blockIdx.y * 64, nb = blockIdx.x * 64;
    float acc[4][4] = {};
    for (int kb = 0; kb < D_N; kb += 16) {
        {
            int r = tid >> 2, kq = (tid & 3) * 4;
            float4 va = *(const float4*)(x + (size_t)(mb + r) * D_N + kb + kq);
            As[kq + 0][r] = va.x; As[kq + 1][r] = va.y;
            As[kq + 2][r] = va.z; As[kq + 3][r] = va.w;
        }
        {
            int kr = tid >> 4, c = (tid & 15) * 4;
            float4 vb = *(const float4*)(W + (size_t)(kb + kr) * H_N + nb + c);
            *(float4*)&Bs[kr][c] = vb;
        }
        __syncthreads();
        #pragma unroll
        for (int k = 0; k < 16; k++) {
            float a[4], bv[4];
            #pragma unroll
            for (int i = 0; i < 4; i++) a[i] = As[k][ty * 4 + i];
            #pragma unroll
            for (int j = 0; j < 4; j++) bv[j] = Bs[k][tx * 4 + j];
            #pragma unroll
            for (int i = 0; i < 4; i++)
                #pragma unroll
                for (int j = 0; j < 4; j++)
                    acc[i][j] = fmaf(a[i], bv[j], acc[i][j]);
        }
        __syncthreads();
    }
    #pragma unroll
    for (int i = 0; i < 4; i++) {
        int row = mb + ty * 4 + i;
        #pragma unroll
        for (int j = 0; j < 4; j++) {
            int col = nb + tx * 4 + j;
            float v = acc[i][j] + bias[col];
            g_h[(size_t)row * H_N + col] = v > 0.f ? v : 0.f;
        }
    }
}

// ---------------- K3: HMMA x@x.T, 512 threads, warp tile 16x32, 3-stage ------
// grid (64 row-tiles, 4 col-quarters); 512 threads (8x2 warp grid); 2 CTA/SM
// SMEM per stage: A 16KB + B 8KB = 24KB; 3 stages; then lists
#define NN_STAGE    24576
#define NN_BOFF     16384
#define NN_TV_OFF   (3 * NN_STAGE)                   // 73728
#define NN_TI_OFF   (NN_TV_OFF + 256 * 16 * 4)       // 90112
#define NN_TMIN_OFF (NN_TI_OFF + 256 * 16 * 2)       // 98304
#define NN_SQC_OFF  (NN_TMIN_OFF + 256 * 4)          // 99328
#define NN_SMEM     (NN_SQC_OFF + 2 * 64 * 4)        // 99840
#define NN_TILES    (2048 / 64)      // 32 col tiles per quarter
#define NN_SLABS    18               // 1152 / 64

__device__ __forceinline__ void load_slab(uint32_t smem_u32, int stage,
                                          int mb, int cb, int t, int tid) {
    uint32_t sbase = smem_u32 + stage * NN_STAGE;
    // A: 128 rows x 128B = 1024 chunks of 16B; 2 per thread
    #pragma unroll
    for (int i = 0; i < 2; i++) {
        int c = tid + i * 512;
        int row = c >> 3, j = c & 7;
        uint32_t dst = SWZ((uint32_t)(row * 128 + j * 16));
        cp16(sbase + dst, g_a + (size_t)(mb + row) * KE + t * 64 + j * 8);
    }
    // B: 64 rows x 128B = 512 chunks; 1 per thread
    {
        int c = tid;
        int row = c >> 3, j = c & 7;
        uint32_t dst = SWZ((uint32_t)(row * 128 + j * 16));
        cp16(sbase + NN_BOFF + dst, g_b + (size_t)(cb + row) * KE + t * 64 + j * 8);
    }
    cp_commit();
}

__global__ __launch_bounds__(512, 2) void k_nn() {
    extern __shared__ __align__(1024) char smem[];
    uint32_t smem_u32 = smem_addr_u32(smem);
    float*          tv   = (float*)(smem + NN_TV_OFF);    // 256 lists x 16
    unsigned short* ti   = (unsigned short*)(smem + NN_TI_OFF);
    float*          tmin = (float*)(smem + NN_TMIN_OFF);  // 256
    float*          sqc  = (float*)(smem + NN_SQC_OFF);   // [2][64]

    int tid = threadIdx.x, lane = tid & 31, wid = tid >> 5;
    int mr = wid >> 1, nc = wid & 1;      // warp grid 8x2
    int mb = blockIdx.x * 128;
    int colbase = blockIdx.y * 2048;

    for (int i = tid; i < 256 * 16; i += 512) { tv[i] = -FLT_MAX; ti[i] = 0xFFFF; }
    if (tid < 256) tmin[tid] = -FLT_MAX;

    int lrow = lane & 15, lkoff = (lane >> 4) * 16;
    int q4 = lane & 3;
    int r0 = mr * 16 + (lane >> 2);
    int r1 = r0 + 8;
    int l0 = r0 * 2 + nc, l1 = r1 * 2 + nc;

    // prologue: stages 0,1 of tile 0 + sq
    load_slab(smem_u32, 0, mb, colbase, 0, tid);
    load_slab(smem_u32, 1, mb, colbase, 1, tid);
    if (tid < 64) sqc[tid] = g_sq[colbase + tid];

    #pragma unroll 1
    for (int ct = 0; ct < NN_TILES; ct++) {
        float acc[4][4];
        #pragma unroll
        for (int ni = 0; ni < 4; ni++)
            #pragma unroll
            for (int q = 0; q < 4; q++) acc[ni][q] = 0.f;

        #pragma unroll 1
        for (int s = 0; s < NN_SLABS; s++) {
            if (s == NN_SLABS - 1)
                asm volatile("cp.async.wait_group 0;" ::: "memory");
            else
                asm volatile("cp.async.wait_group 1;" ::: "memory");
            __syncthreads();

            if (s + 2 < NN_SLABS)
                load_slab(smem_u32, (s + 2) % 3, mb, colbase + ct * 64, s + 2, tid);

            uint32_t sbase = smem_u32 + (s % 3) * NN_STAGE;
            uint32_t aBase = sbase;
            uint32_t bBase = sbase + NN_BOFF;

            #pragma unroll
            for (int kk = 0; kk < 4; kk++) {
                uint32_t af[4];
                {
                    int row = mr * 16 + lrow;
                    uint32_t off = SWZ((uint32_t)(row * 128 + kk * 32 + lkoff));
                    ldsm4(af[0], af[1], af[2], af[3], aBase + off);
                }
                #pragma unroll
                for (int bi = 0; bi < 2; bi++) {
                    int row = nc * 32 + bi * 16 + lrow;
                    uint32_t off = SWZ((uint32_t)(row * 128 + kk * 32 + lkoff));
                    uint32_t b0, b1, b2, b3;
                    ldsm4(b0, b1, b2, b3, bBase + off);
                    mma16816(acc[bi * 2 + 0], af, b0, b2);
                    mma16816(acc[bi * 2 + 1], af, b1, b3);
                }
            }
        }

        // prefetch next tile stages 0,1 + sq (overlaps epilogue; stages 0/1
        // were consumed >= 2 barriers ago)
        if (ct + 1 < NN_TILES) {
            int cbn = colbase + (ct + 1) * 64;
            load_slab(smem_u32, 0, mb, cbn, 0, tid);
            load_slab(smem_u32, 1, mb, cbn, 1, tid);
            if (tid < 64) sqc[((ct + 1) & 1) * 64 + tid] = g_sq[cbn + tid];
        }

        // ---- register epilogue: 2 rows/lane, lists keyed (row, nc) ----
        const float* sqp = sqc + (ct & 1) * 64;
        float m0 = tmin[l0], m1 = tmin[l1];
        bool hit = false;
        #pragma unroll
        for (int ni = 0; ni < 4; ni++) {
            int c0 = nc * 32 + ni * 8 + 2 * q4;
            float s0 = sqp[c0], s1 = sqp[c0 + 1];
            float k0 = fmaf(2.f, acc[ni][0], -s0);
            float k1 = fmaf(2.f, acc[ni][1], -s1);
            float k2 = fmaf(2.f, acc[ni][2], -s0);
            float k3 = fmaf(2.f, acc[ni][3], -s1);
            hit |= (k0 > m0) | (k1 > m0) | (k2 > m1) | (k3 > m1);
        }
        unsigned mask = __ballot_sync(0xffffffffu, hit);
        if (mask) {
            #pragma unroll 1
            for (int phase = 0; phase < 4; phase++) {
                if (q4 == phase && hit) {
                    float cm0 = tmin[l0], cm1 = tmin[l1];
                    float* rv0 = tv + l0 * 16; unsigned short* rx0 = ti + l0 * 16;
                    float* rv1 = tv + l1 * 16; unsigned short* rx1 = ti + l1 * 16;
                    #pragma unroll 1
                    for (int ni = 0; ni < 4; ni++) {
                        int cl = nc * 32 + ni * 8 + 2 * q4;
                        float s0 = sqp[cl], s1 = sqp[cl + 1];
                        float k0 = fmaf(2.f, acc[ni][0], -s0);
                        float k1 = fmaf(2.f, acc[ni][1], -s1);
                        float k2 = fmaf(2.f, acc[ni][2], -s0);
                        float k3 = fmaf(2.f, acc[ni][3], -s1);
                        int c0 = ct * 64 + cl;
                        if (k0 > cm0) ins16(rv0, rx0, k0, c0, cm0);
                        if (k1 > cm0) ins16(rv0, rx0, k1, c0 + 1, cm0);
                        if (k2 > cm1) ins16(rv1, rx1, k2, c0, cm1);
                        if (k3 > cm1) ins16(rv1, rx1, k3, c0 + 1, cm1);
                    }
                    tmin[l0] = cm0; tmin[l1] = cm1;
                }
                __syncwarp();
            }
        }
        // lists keyed (row,nc) are warp-exclusive; ring/sqc protected by syncs
    }

    __syncthreads();

    // ---- sort each of the 256 lists by (v desc, idx asc) and write out ----
    if (tid < 256) {
        float* rv = tv + tid * 16;
        unsigned short* rx = ti + tid * 16;
        for (int a = 1; a < 16; a++) {
            float v = rv[a]; int id = rx[a]; int b2 = a - 1;
            while (b2 >= 0 && (rv[b2] < v || (rv[b2] == v && rx[b2] > id))) {
                rv[b2 + 1] = rv[b2]; rx[b2 + 1] = rx[b2]; b2--;
            }
            rv[b2 + 1] = v; rx[b2 + 1] = (unsigned short)id;
        }
        int row = mb + (tid >> 1);
        int l   = blockIdx.y * 2 + (tid & 1);      // 8 global lists per row
        size_t base = ((size_t)l * B_N + row) * KMAX;
        for (int s = 0; s < 16; s++) {
            g_topv[base + s] = rv[s];
            g_topi[base + s] = colbase + (int)rx[s];
        }
    }
}

// ---------------- K3b: 8-way merge of per-list top-16 ------------------------
__global__ void k_merge() {
    int row = blockIdx.x * 256 + threadIdx.x;
    if (row >= B_N) return;
    const float* V[8]; const int* I[8];
    int a[8];
    #pragma unroll
    for (int l = 0; l < 8; l++) {
        V[l] = g_topv + ((size_t)l * B_N + row) * KMAX;
        I[l] = g_topi + ((size_t)l * B_N + row) * KMAX;
        a[l] = 0;
    }
    int* out = g_idx + (size_t)row * KMAX;
    for (int s = 0; s < 16; s++) {
        int bl = -1; float bv = 0.f; int bi = 0;
        #pragma unroll
        for (int l = 0; l < 8; l++) {
            float v = V[l][a[l]]; int id = I[l][a[l]];
            if (bl < 0 || v > bv || (v == bv && id < bi)) { bl = l; bv = v; bi = id; }
        }
        out[s] = bi; a[bl]++;
    }
}

// ---------------- K4: gather-mean -> W_res -> relu -> +h -> LN -> fc ---------
__global__ __launch_bounds__(256) void k_tail(const float* __restrict__ Wres,
                                              const float* __restrict__ bres,
                                              const float* __restrict__ lng,
                                              const float* __restrict__ lnb,
                                              const float* __restrict__ Wfc,
                                              const float* __restrict__ bfc,
                                              float* __restrict__ out) {
    extern __shared__ float sm[];
    float* agg  = sm;
    float* hs   = agg + 16 * H_N;
    float* Ws   = hs + 16 * H_N;
    int*   idxs = (int*)(Ws + 32 * H_N);
    int*   ks   = idxs + 16 * 16;

    int tid = threadIdx.x;
    int rb = blockIdx.x * 16;
    {
        int r = tid >> 4, j = tid & 15;
        idxs[tid] = g_idx[(size_t)(rb + r) * KMAX + j];
    }
    if (tid < 16) ks[tid] = g_k[rb + tid];
    __syncthreads();

    int c = tid;
    for (int r = 0; r < 16; r++) {
        int kr = ks[r];
        float s = 0.f;
        for (int j = 0; j < kr; j++)
            s += g_h[(size_t)idxs[r * 16 + j] * H_N + c];
        agg[r * H_N + c] = s / (float)kr;
        hs[r * H_N + c]  = g_h[(size_t)(rb + r) * H_N + c];
    }
    __syncthreads();

    float acc[16];
    #pragma unroll
    for (int r = 0; r < 16; r++) acc[r] = 0.f;
    for (int kb = 0; kb < H_N; kb += 32) {
        __syncthreads();
        for (int kk = 0; kk < 32; kk++)
            Ws[kk * H_N + c] = Wres[(size_t)(kb + kk) * H_N + c];
        __syncthreads();
        for (int kk = 0; kk < 32; kk++) {
            float w = Ws[kk * H_N + c];
            #pragma unroll
            for (int r = 0; r < 16; r++)
                acc[r] = fmaf(agg[r * H_N + kb + kk], w, acc[r]);
        }
    }
    __syncthreads();

    float brc = bres[c];
    for (int r = 0; r < 16; r++) {
        float rv = acc[r] + brc;
        rv = rv > 0.f ? rv : 0.f;
        agg[r * H_N + c] = hs[r * H_N + c] + rv;
    }
    __syncthreads();

    int lane = tid & 31, wid = tid >> 5;
    for (int rr = 0; rr < 2; rr++) {
        int r = wid * 2 + rr;
        int row = rb + r;
        float* z = agg + r * H_N;
        float s = 0.f;
        #pragma unroll
        for (int t = 0; t < 8; t++) s += z[lane + 32 * t];
        #pragma unroll
        for (int o = 16; o; o >>= 1) s += __shfl_xor_sync(0xffffffffu, s, o);
        float mu = s * (1.f / 256.f);
        float vs = 0.f;
        #pragma unroll
        for (int t = 0; t < 8; t++) {
            float d = z[lane + 32 * t] - mu;
            vs = fmaf(d, d, vs);
        }
        #pragma unroll
        for (int o = 16; o; o >>= 1) vs += __shfl_xor_sync(0xffffffffu, vs, o);
        float rstd = rsqrtf(vs * (1.f / 256.f) + 1e-5f);

        float vals[8];
        #pragma unroll
        for (int t = 0; t < 8; t++) {
            int col = lane + 32 * t;
            float zn = (z[col] - mu) * rstd;
            vals[t] = zn * lng[col] + lnb[col];
        }
        #pragma unroll
        for (int cc = 0; cc < C_N; cc++) {
            float p = 0.f;
            #pragma unroll
            for (int t = 0; t < 8; t++) {
                int col = lane + 32 * t;
                p = fmaf(vals[t], Wfc[(size_t)col * C_N + cc], p);
            }
            #pragma unroll
            for (int o = 16; o; o >>= 1) p += __shfl_xor_sync(0xffffffffu, p, o);
            if (lane == 0) out[(size_t)row * C_N + cc] = p + bfc[cc];
        }
    }
}

// ---------------- launch ------------------------------------------------------
extern "C" void kernel_launch(void* const* d_in, const int* in_sizes, int n_in,
                              void* d_out, int out_size) {
    const float* x  = (const float*)d_in[0];
    const float* Wp = (const float*)d_in[1];
    const float* bp = (const float*)d_in[2];
    const float* Wt = (const float*)d_in[3];
    const float* bt = (const float*)d_in[4];
    const float* Wr = (const float*)d_in[5];
    const float* br = (const float*)d_in[6];
    const float* lg = (const float*)d_in[7];
    const float* lb = (const float*)d_in[8];
    const float* Wf = (const float*)d_in[9];
    const float* bf = (const float*)d_in[10];
    float* out = (float*)d_out;

    const int SMEM_TAIL = (16 * 256 * 2 + 32 * 256 + 16 * 16 + 16) * 4;
    cudaFuncSetAttribute(k_tail, cudaFuncAttributeMaxDynamicSharedMemorySize, SMEM_TAIL);
    cudaFuncSetAttribute(k_nn,   cudaFuncAttributeMaxDynamicSharedMemorySize, NN_SMEM);

    k_cvt<<<B_N, D_N>>>(x);
    k_sqtau<<<B_N / 8, dim3(32, 8)>>>(x, Wt, bt);
    k_proj<<<dim3(H_N / 64, B_N / 64), 256>>>(x, Wp, bp);
    k_nn<<<dim3(B_N / 128, NPART), 512, NN_SMEM>>>();
    k_merge<<<B_N / 256, 256>>>();
    k_tail<<<B_N / 16, 256, SMEM_TAIL>>>(Wr, br, lg, lb, Wf, bf, out);
}